// round 9
// baseline (speedup 1.0000x reference)
#include <cuda_runtime.h>
#include <cstdint>

// IOVPreTrainedEmbeddings: out[b,s,:] = (oov_map[x[b,s]] >= 0)
//                                         ? oov_embed[oov_map[x[b,s]], :]
//                                         : w2v[x[b,s], :]
//
// x [131072] i32, w2v [100000,300] f32, oov_embed [5000,300] f32,
// oov_map [100000] i32, out [131072,300] f32.
//
// R8: write-through stores (__stwt / STG.WT) + evict_last pinned loads.
// R7 showed pinning helps the timed (warm) loop only slightly; hypothesis:
// the 157MB write stream write-allocates in L2 and evicts the pinned
// ~94MB read set each replay. WT stores don't retain lines in L2, leaving
// the full 126MB for the tables. Steady state target: reads ~0 from DRAM,
// write-bound kernel.

static constexpr int TOKENS = 128 * 1024;     // B*S
static constexpr int DIM    = 300;
static constexpr int VEC    = DIM / 4;        // 75 float4 per row (1200B stride)
static constexpr long long TOTAL4 = (long long)TOKENS * VEC;  // 9,830,400

static constexpr int THREADS = 256;
static constexpr int UNROLL  = 8;
static constexpr int BLOCKS  = (int)(TOTAL4 / ((long long)THREADS * UNROLL)); // 4800, exact
static constexpr int STRIDE  = THREADS * BLOCKS;  // 1,228,800

__device__ __forceinline__ uint64_t policy_evict_last() {
    uint64_t pol;
    asm("createpolicy.fractional.L2::evict_last.b64 %0, 1.0;" : "=l"(pol));
    return pol;
}

__device__ __forceinline__ int ldg_i32_el(const int* p, uint64_t pol) {
    int v;
    asm volatile("ld.global.nc.L2::cache_hint.b32 %0, [%1], %2;"
                 : "=r"(v) : "l"(p), "l"(pol));
    return v;
}

__device__ __forceinline__ float4 ldg_f4_el(const float4* p, uint64_t pol) {
    float4 v;
    asm volatile("ld.global.nc.L2::cache_hint.v4.f32 {%0,%1,%2,%3}, [%4], %5;"
                 : "=f"(v.x), "=f"(v.y), "=f"(v.z), "=f"(v.w)
                 : "l"(p), "l"(pol));
    return v;
}

__global__ __launch_bounds__(THREADS)
void iov_gather_wt_kernel(const int*    __restrict__ x,
                          const float4* __restrict__ w2v,       // row stride VEC
                          const float4* __restrict__ oov_embed, // row stride VEC
                          const int*    __restrict__ oov_map,
                          float4*       __restrict__ out)
{
    const int base = blockIdx.x * THREADS + threadIdx.x;
    const uint64_t pol = policy_evict_last();

    int id[UNROLL];
    int row[UNROLL];

    // Phase 1: token ids (small, pinned).
    #pragma unroll
    for (int k = 0; k < UNROLL; k++) {
        int token = (base + k * STRIDE) / VEC;   // mul-shift div by 75
        id[k] = ldg_i32_el(&x[token], pol);
    }

    // Phase 2: oov_map gathers (400KB table, pinned).
    #pragma unroll
    for (int k = 0; k < UNROLL; k++)
        row[k] = ldg_i32_el(&oov_map[id[k]], pol);

    // Phase 3+4: payload gather (evict_last -> tables stay L2-resident
    // across graph replays) + write-through store (no L2 line retention,
    // no pollution of the pinned set).
    #pragma unroll
    for (int k = 0; k < UNROLL; k++) {
        int i     = base + k * STRIDE;
        int token = i / VEC;
        int chunk = i - token * VEC;
        const float4* src = (row[k] >= 0)
            ? (oov_embed + (long long)row[k] * VEC + chunk)
            : (w2v       + (long long)id[k]  * VEC + chunk);
        float4 v = ldg_f4_el(src, pol);
        __stwt(&out[i], v);
    }
}

extern "C" void kernel_launch(void* const* d_in, const int* in_sizes, int n_in,
                              void* d_out, int out_size)
{
    const int*    x         = (const int*)   d_in[0];
    const float4* w2v       = (const float4*)d_in[1];
    const float4* oov_embed = (const float4*)d_in[2];
    const int*    oov_map   = (const int*)   d_in[3];
    float4*       out       = (float4*)d_out;

    iov_gather_wt_kernel<<<BLOCKS, THREADS>>>(x, w2v, oov_embed, oov_map, out);
}